// round 2
// baseline (speedup 1.0000x reference)
#include <cuda_runtime.h>
#include <cuda_bf16.h>
#include <cmath>

#define N_NODES 20000
#define N_EDGES 320000
#define MAXD    1024

// ---------------- scratch (static __device__, no allocs) ----------------
__device__ float g_bufA[(size_t)N_NODES * MAXD];   // ping
__device__ float g_bufB[(size_t)N_NODES * MAXD];   // pong
__device__ float g_H   [(size_t)N_NODES * MAXD];   // GEMM output per layer
__device__ float g_el[N_NODES];
__device__ float g_er[N_NODES];
__device__ int   g_rowptr[N_NODES + 1];
__device__ int   g_cnt[N_NODES];
__device__ int   g_fill[N_NODES];
__device__ int   g_csrc[N_EDGES];
__device__ float g_pool[MAXD];

// ---------------- CSR build ----------------
__global__ void zero_kernel() {
    int i = blockIdx.x * blockDim.x + threadIdx.x;
    if (i < N_NODES) { g_cnt[i] = 0; g_fill[i] = 0; }
}

__global__ void count_kernel(const int* __restrict__ dst) {
    int e = blockIdx.x * blockDim.x + threadIdx.x;
    if (e < N_EDGES) atomicAdd(&g_cnt[dst[e]], 1);
}

__global__ void scan_kernel() {
    __shared__ int sd[1024];
    __shared__ int carry;
    if (threadIdx.x == 0) carry = 0;
    __syncthreads();
    for (int base = 0; base < N_NODES; base += 1024) {
        int i = base + threadIdx.x;
        int v = (i < N_NODES) ? g_cnt[i] : 0;
        sd[threadIdx.x] = v;
        __syncthreads();
        for (int off = 1; off < 1024; off <<= 1) {
            int t = (threadIdx.x >= off) ? sd[threadIdx.x - off] : 0;
            __syncthreads();
            sd[threadIdx.x] += t;
            __syncthreads();
        }
        if (i < N_NODES) g_rowptr[i] = carry + sd[threadIdx.x] - v;
        __syncthreads();
        if (threadIdx.x == 0) carry += sd[1023];
        __syncthreads();
    }
    if (threadIdx.x == 0) g_rowptr[N_NODES] = carry;
}

__global__ void fill_kernel(const int* __restrict__ src, const int* __restrict__ dst) {
    int e = blockIdx.x * blockDim.x + threadIdx.x;
    if (e < N_EDGES) {
        int d = dst[e];
        int p = atomicAdd(&g_fill[d], 1);
        g_csrc[g_rowptr[d] + p] = src[e];
    }
}

// ---------------- GEMM: C[M,N] = A[M,K] @ B[K,N], row-major fp32 ----------------
#define BM 128
#define BN 64
#define BK 16
#define TM 8
#define TN 4

__global__ __launch_bounds__(256) void gemm_kernel(
    const float* __restrict__ A, const float* __restrict__ B,
    float* __restrict__ C, int M, int K, int N)
{
    __shared__ float As[BK][BM + 4];
    __shared__ float Bs[BK][BN];

    int tid = threadIdx.x;
    int tx = tid & 15;       // 0..15 column group
    int ty = tid >> 4;       // 0..15 row group
    int row0 = blockIdx.y * BM;
    int col0 = blockIdx.x * BN;

    float acc[TM][TN];
#pragma unroll
    for (int i = 0; i < TM; i++)
#pragma unroll
        for (int j = 0; j < TN; j++) acc[i][j] = 0.f;

    for (int k0 = 0; k0 < K; k0 += BK) {
        // A tile: BM x BK = 2048 elems, 8 per thread
#pragma unroll
        for (int i = 0; i < 8; i++) {
            int idx = tid + i * 256;
            int m  = idx >> 4;
            int kk = idx & 15;
            int gm = row0 + m;
            As[kk][m] = (gm < M) ? A[(size_t)gm * K + k0 + kk] : 0.f;
        }
        // B tile: BK x BN = 1024 elems, 4 per thread (K,N multiples of 16/64)
#pragma unroll
        for (int i = 0; i < 4; i++) {
            int idx = tid + i * 256;
            int kk = idx >> 6;
            int n  = idx & 63;
            Bs[kk][n] = B[(size_t)(k0 + kk) * N + col0 + n];
        }
        __syncthreads();

#pragma unroll
        for (int kk = 0; kk < BK; kk++) {
            float a[TM], b[TN];
#pragma unroll
            for (int i = 0; i < TM; i++) a[i] = As[kk][ty * TM + i];
#pragma unroll
            for (int j = 0; j < TN; j++) b[j] = Bs[kk][tx * TN + j];
#pragma unroll
            for (int i = 0; i < TM; i++)
#pragma unroll
                for (int j = 0; j < TN; j++) acc[i][j] += a[i] * b[j];
        }
        __syncthreads();
    }

#pragma unroll
    for (int i = 0; i < TM; i++) {
        int gm = row0 + ty * TM + i;
        if (gm < M) {
#pragma unroll
            for (int j = 0; j < TN; j++)
                C[(size_t)gm * N + col0 + tx * TN + j] = acc[i][j];
        }
    }
}

// ---------------- per-node el / er (one warp per node) ----------------
__global__ void elr_kernel(const float* __restrict__ H,
                           const float* __restrict__ al,
                           const float* __restrict__ ar, int dout)
{
    int g = blockIdx.x * blockDim.x + threadIdx.x;
    int node = g >> 5, lane = g & 31;
    if (node >= N_NODES) return;
    const float* row = H + (size_t)node * dout;
    float sl = 0.f, sr = 0.f;
    for (int c = lane; c < dout; c += 32) {
        float v = row[c];
        sl += v * al[c];
        sr += v * ar[c];
    }
#pragma unroll
    for (int o = 16; o > 0; o >>= 1) {
        sl += __shfl_down_sync(0xffffffffu, sl, o);
        sr += __shfl_down_sync(0xffffffffu, sr, o);
    }
    if (lane == 0) { g_el[node] = sl; g_er[node] = sr; }
}

// ---------------- fused softmax-aggregation, one block per dst node ----------------
// online softmax over edge chunks; NC channels per thread
template <int NC>
__global__ __launch_bounds__(256) void agg_kernel(
    const float* __restrict__ H, const float* __restrict__ bias,
    float* __restrict__ Y, int dout)
{
    int n   = blockIdx.x;
    int bd  = blockDim.x;
    int tid = threadIdx.x;
    int beg = g_rowptr[n], end = g_rowptr[n + 1];
    float er_n = g_er[n];

    __shared__ float s_w[256];
    __shared__ int   s_s[256];
    __shared__ float s_red[256];

    float acc[NC];
#pragma unroll
    for (int r = 0; r < NC; r++) acc[r] = 0.f;
    float m = -INFINITY;
    float ssum = 0.f;

    for (int base = beg; base < end; base += bd) {
        int cnt = min(bd, end - base);
        float e = -INFINITY;
        int sj = 0;
        if (tid < cnt) {
            sj = g_csrc[base + tid];
            float x = g_el[sj] + er_n;
            e = x > 0.f ? x : 0.2f * x;
        }
        s_s[tid] = sj;
        s_red[tid] = e;
        __syncthreads();
        for (int o = bd >> 1; o > 0; o >>= 1) {
            if (tid < o) s_red[tid] = fmaxf(s_red[tid], s_red[tid + o]);
            __syncthreads();
        }
        float nm = fmaxf(m, s_red[0]);
        __syncthreads();

        float w = (tid < cnt) ? __expf(e - nm) : 0.f;
        s_w[tid] = w;
        s_red[tid] = w;
        __syncthreads();
        for (int o = bd >> 1; o > 0; o >>= 1) {
            if (tid < o) s_red[tid] += s_red[tid + o];
            __syncthreads();
        }
        float csum = s_red[0];

        float scale = (m == -INFINITY) ? 0.f : __expf(m - nm);
        ssum = ssum * scale + csum;
#pragma unroll
        for (int r = 0; r < NC; r++) acc[r] *= scale;

        for (int q = 0; q < cnt; q++) {
            float wq = s_w[q];
            const float* hr = H + (size_t)s_s[q] * dout;
#pragma unroll
            for (int r = 0; r < NC; r++)
                acc[r] += wq * hr[tid + r * bd];
        }
        m = nm;
        __syncthreads();
    }

    float inv = (end > beg) ? 1.f / ssum : 0.f;
#pragma unroll
    for (int r = 0; r < NC; r++) {
        int c = tid + r * bd;
        Y[(size_t)n * dout + c] = tanhf(acc[r] * inv + bias[c]);
    }
}

// ---------------- readout ----------------
__global__ void pool_kernel(const float* __restrict__ Y, const int* __restrict__ order) {
    int c = blockIdx.x * blockDim.x + threadIdx.x;   // 0..1023
    int rows = order[0] + 1;
    float s = 0.f;
    for (int r = 0; r < rows; r++) s += Y[(size_t)r * MAXD + c];
    g_pool[c] = s / (float)rows;
}

__global__ void logits_kernel(const float* __restrict__ relW,
                              const float* __restrict__ relB,
                              const int* __restrict__ rel,
                              float* __restrict__ out)
{
    int t = threadIdx.x;   // 64 threads
    float s = relB[t];
    for (int k = 0; k < MAXD; k++) s += g_pool[k] * relW[k * 64 + t];
    __shared__ float lg[64];
    lg[t] = s;
    __syncthreads();
    if (t == 0) {
        int idx[64];
        int cnt = 0;
        for (int i = 0; i < 64; i++)
            if (rel[i] != 0) idx[cnt++] = i;
        for (int k = cnt; k < 64; k++) idx[k] = 0;   // jnp.nonzero pad fill=0
        for (int k = 0; k < 64; k++) out[k] = lg[idx[k]];
    }
}

// ---------------- launch ----------------
extern "C" void kernel_launch(void* const* d_in, const int* in_sizes, int n_in,
                              void* d_out, int out_size)
{
    const float* feat  = (const float*)d_in[0];
    const float* W[4]  = {(const float*)d_in[1], (const float*)d_in[5],
                          (const float*)d_in[9], (const float*)d_in[13]};
    const float* al[4] = {(const float*)d_in[2], (const float*)d_in[6],
                          (const float*)d_in[10], (const float*)d_in[14]};
    const float* ar[4] = {(const float*)d_in[3], (const float*)d_in[7],
                          (const float*)d_in[11], (const float*)d_in[15]};
    const float* bb[4] = {(const float*)d_in[4], (const float*)d_in[8],
                          (const float*)d_in[12], (const float*)d_in[16]};
    const float* relW  = (const float*)d_in[17];
    const float* relB  = (const float*)d_in[18];
    const int*   src   = (const int*)d_in[19];
    const int*   dst   = (const int*)d_in[20];
    const int*   rel   = (const int*)d_in[21];
    const int*   order = (const int*)d_in[22];
    float* out = (float*)d_out;

    float *pA, *pB, *pH;
    cudaGetSymbolAddress((void**)&pA, g_bufA);
    cudaGetSymbolAddress((void**)&pB, g_bufB);
    cudaGetSymbolAddress((void**)&pH, g_H);

    // CSR (by dst) — rebuilt every launch, deterministic work
    zero_kernel <<<(N_NODES + 255) / 256, 256>>>();
    count_kernel<<<(N_EDGES + 255) / 256, 256>>>(dst);
    scan_kernel <<<1, 1024>>>();
    fill_kernel <<<(N_EDGES + 255) / 256, 256>>>(src, dst);

    const int din_a [4] = {64, 128, 256, 512};
    const int dout_a[4] = {128, 256, 512, 1024};

    const float* x = feat;
    float* outbufs[4] = {pA, pB, pA, pB};

    for (int l = 0; l < 4; l++) {
        int din = din_a[l], dout = dout_a[l];
        dim3 grid(dout / BN, (N_NODES + BM - 1) / BM);
        gemm_kernel<<<grid, 256>>>(x, W[l], pH, N_NODES, din, dout);

        elr_kernel<<<(N_NODES * 32 + 255) / 256, 256>>>(pH, al[l], ar[l], dout);

        float* y = outbufs[l];
        switch (dout) {
            case 128:  agg_kernel<1><<<N_NODES, 128>>>(pH, bb[l], y, dout); break;
            case 256:  agg_kernel<1><<<N_NODES, 256>>>(pH, bb[l], y, dout); break;
            case 512:  agg_kernel<2><<<N_NODES, 256>>>(pH, bb[l], y, dout); break;
            default:   agg_kernel<4><<<N_NODES, 256>>>(pH, bb[l], y, dout); break;
        }
        x = y;
    }

    pool_kernel<<<MAXD / 256, 256>>>(pB, order);
    logits_kernel<<<1, 64>>>(relW, relB, rel, out);
}

// round 4
// speedup vs baseline: 1.5568x; 1.5568x over previous
#include <cuda_runtime.h>
#include <cuda_bf16.h>
#include <cmath>

#define N_NODES 20000
#define N_EDGES 320000
#define MAXD    1024

// ---------------- scratch (static __device__, no allocs) ----------------
__device__ float g_bufA[(size_t)N_NODES * MAXD];   // ping
__device__ float g_bufB[(size_t)N_NODES * MAXD];   // pong
__device__ float g_H   [(size_t)N_NODES * MAXD];   // GEMM output per layer
__device__ float g_el[N_NODES];
__device__ float g_er[N_NODES];
__device__ int   g_rowptr[N_NODES + 1];
__device__ int   g_cnt[N_NODES];
__device__ int   g_fill[N_NODES];
__device__ int   g_csrc[N_EDGES];
__device__ float g_pool[MAXD];

// ---------------- CSR build ----------------
__global__ void zero_kernel() {
    int i = blockIdx.x * blockDim.x + threadIdx.x;
    if (i < N_NODES) { g_cnt[i] = 0; g_fill[i] = 0; }
}

__global__ void count_kernel(const int* __restrict__ dst) {
    int e = blockIdx.x * blockDim.x + threadIdx.x;
    if (e < N_EDGES) atomicAdd(&g_cnt[dst[e]], 1);
}

__global__ void scan_kernel() {
    __shared__ int sd[1024];
    __shared__ int carry;
    if (threadIdx.x == 0) carry = 0;
    __syncthreads();
    for (int base = 0; base < N_NODES; base += 1024) {
        int i = base + threadIdx.x;
        int v = (i < N_NODES) ? g_cnt[i] : 0;
        sd[threadIdx.x] = v;
        __syncthreads();
        for (int off = 1; off < 1024; off <<= 1) {
            int t = (threadIdx.x >= off) ? sd[threadIdx.x - off] : 0;
            __syncthreads();
            sd[threadIdx.x] += t;
            __syncthreads();
        }
        if (i < N_NODES) g_rowptr[i] = carry + sd[threadIdx.x] - v;
        __syncthreads();
        if (threadIdx.x == 0) carry += sd[1023];
        __syncthreads();
    }
    if (threadIdx.x == 0) g_rowptr[N_NODES] = carry;
}

__global__ void fill_kernel(const int* __restrict__ src, const int* __restrict__ dst) {
    int e = blockIdx.x * blockDim.x + threadIdx.x;
    if (e < N_EDGES) {
        int d = dst[e];
        int p = atomicAdd(&g_fill[d], 1);
        g_csrc[g_rowptr[d] + p] = src[e];
    }
}

// ---------------- tf32 tensor-core GEMM ----------------
// C[M,N] = A[M,K] @ B[K,N], all row-major fp32, tf32 MMA with fp32 accumulate.
// Block tile 128x128x16, 256 threads = 8 warps (2m x 4n), warp tile 64x32.
#define GBM 128
#define GBN 128
#define GBK 16
#define AST (GBK + 4)    // As row stride = 20 floats (bank-conflict-free frags)
#define BST (GBN + 8)    // Bs row stride = 136 floats

__device__ __forceinline__ unsigned f2tf32(float f) {
    unsigned u;
    asm("cvt.rna.tf32.f32 %0, %1;" : "=r"(u) : "f"(f));
    return u;
}

__device__ __forceinline__ void cp_async16(void* smem_dst, const void* gsrc) {
    unsigned s = (unsigned)__cvta_generic_to_shared(smem_dst);
    asm volatile("cp.async.cg.shared.global [%0], [%1], 16;\n" :: "r"(s), "l"(gsrc));
}

__global__ __launch_bounds__(256) void gemm_tf32_kernel(
    const float* __restrict__ A, const float* __restrict__ B,
    float* __restrict__ C, int M, int K, int N)
{
    __shared__ __align__(16) float As[2][GBM][AST];
    __shared__ __align__(16) float Bs[2][GBK][BST];

    int tid  = threadIdx.x;
    int lane = tid & 31;
    int warp = tid >> 5;
    int wm = (warp >> 2) * 64;      // warp m-offset within block tile
    int wn = (warp & 3) * 32;       // warp n-offset
    int g = lane >> 2;              // groupID 0..7
    int t = lane & 3;               // tid-in-group 0..3

    int row0 = blockIdx.y * GBM;
    int col0 = blockIdx.x * GBN;

    float acc[4][4][4];
#pragma unroll
    for (int mi = 0; mi < 4; mi++)
#pragma unroll
        for (int ni = 0; ni < 4; ni++)
#pragma unroll
            for (int r = 0; r < 4; r++) acc[mi][ni][r] = 0.f;

    int nk = K / GBK;

    // ---- stage loader ----
    auto load_stage = [&](int it, int buf) {
#pragma unroll
        for (int i = 0; i < 2; i++) {
            int c = tid + i * 256;           // 512 float4 chunks for A
            int m  = c >> 2;
            int kq = c & 3;
            int gm = row0 + m;
            if (gm >= M) gm = M - 1;         // clamp: rows >=M never stored
            cp_async16(&As[buf][m][kq * 4],
                       A + (size_t)gm * K + it * GBK + kq * 4);
        }
#pragma unroll
        for (int i = 0; i < 2; i++) {
            int c = tid + i * 256;           // 512 float4 chunks for B
            int r  = c >> 5;
            int c4 = c & 31;
            cp_async16(&Bs[buf][r][c4 * 4],
                       B + (size_t)(it * GBK + r) * N + col0 + c4 * 4);
        }
        asm volatile("cp.async.commit_group;\n" ::: "memory");
    };

    load_stage(0, 0);

    for (int it = 0; it < nk; it++) {
        int cur = it & 1;
        if (it + 1 < nk) {
            load_stage(it + 1, cur ^ 1);
            asm volatile("cp.async.wait_group 1;\n" ::: "memory");
        } else {
            asm volatile("cp.async.wait_group 0;\n" ::: "memory");
        }
        __syncthreads();

#pragma unroll
        for (int ks = 0; ks < 2; ks++) {     // two k8 steps per BK=16
            unsigned a[4][4], b[4][2];
#pragma unroll
            for (int mi = 0; mi < 4; mi++) {
                int rb = wm + mi * 16;
                a[mi][0] = f2tf32(As[cur][rb + g    ][ks * 8 + t    ]);
                a[mi][1] = f2tf32(As[cur][rb + g + 8][ks * 8 + t    ]);
                a[mi][2] = f2tf32(As[cur][rb + g    ][ks * 8 + t + 4]);
                a[mi][3] = f2tf32(As[cur][rb + g + 8][ks * 8 + t + 4]);
            }
#pragma unroll
            for (int ni = 0; ni < 4; ni++) {
                int cb = wn + ni * 8 + g;
                b[ni][0] = f2tf32(Bs[cur][ks * 8 + t    ][cb]);
                b[ni][1] = f2tf32(Bs[cur][ks * 8 + t + 4][cb]);
            }
#pragma unroll
            for (int mi = 0; mi < 4; mi++)
#pragma unroll
                for (int ni = 0; ni < 4; ni++) {
                    asm volatile(
                        "mma.sync.aligned.m16n8k8.row.col.f32.tf32.tf32.f32 "
                        "{%0,%1,%2,%3}, {%4,%5,%6,%7}, {%8,%9}, {%0,%1,%2,%3};\n"
                        : "+f"(acc[mi][ni][0]), "+f"(acc[mi][ni][1]),
                          "+f"(acc[mi][ni][2]), "+f"(acc[mi][ni][3])
                        : "r"(a[mi][0]), "r"(a[mi][1]), "r"(a[mi][2]), "r"(a[mi][3]),
                          "r"(b[ni][0]), "r"(b[ni][1]));
                }
        }
        __syncthreads();
    }

    // ---- epilogue ----
#pragma unroll
    for (int mi = 0; mi < 4; mi++) {
        int r0 = row0 + wm + mi * 16 + g;
        int r1 = r0 + 8;
#pragma unroll
        for (int ni = 0; ni < 4; ni++) {
            int cc = col0 + wn + ni * 8 + 2 * t;
            if (r0 < M) {
                C[(size_t)r0 * N + cc]     = acc[mi][ni][0];
                C[(size_t)r0 * N + cc + 1] = acc[mi][ni][1];
            }
            if (r1 < M) {
                C[(size_t)r1 * N + cc]     = acc[mi][ni][2];
                C[(size_t)r1 * N + cc + 1] = acc[mi][ni][3];
            }
        }
    }
}

// ---------------- per-node el / er (one warp per node) ----------------
__global__ void elr_kernel(const float* __restrict__ H,
                           const float* __restrict__ al,
                           const float* __restrict__ ar, int dout)
{
    int g = blockIdx.x * blockDim.x + threadIdx.x;
    int node = g >> 5, lane = g & 31;
    if (node >= N_NODES) return;
    const float* row = H + (size_t)node * dout;
    float sl = 0.f, sr = 0.f;
    for (int c = lane; c < dout; c += 32) {
        float v = row[c];
        sl += v * al[c];
        sr += v * ar[c];
    }
#pragma unroll
    for (int o = 16; o > 0; o >>= 1) {
        sl += __shfl_down_sync(0xffffffffu, sl, o);
        sr += __shfl_down_sync(0xffffffffu, sr, o);
    }
    if (lane == 0) { g_el[node] = sl; g_er[node] = sr; }
}

// ---------------- fused softmax-aggregation, one block per dst node ----------------
template <int NC>
__global__ __launch_bounds__(256) void agg_kernel(
    const float* __restrict__ H, const float* __restrict__ bias,
    float* __restrict__ Y, int dout)
{
    int n   = blockIdx.x;
    int bd  = blockDim.x;
    int tid = threadIdx.x;
    int beg = g_rowptr[n], end = g_rowptr[n + 1];
    float er_n = g_er[n];

    __shared__ float s_w[256];
    __shared__ int   s_s[256];
    __shared__ float s_red[256];

    float acc[NC];
#pragma unroll
    for (int r = 0; r < NC; r++) acc[r] = 0.f;
    float m = -INFINITY;
    float ssum = 0.f;

    for (int base = beg; base < end; base += bd) {
        int cnt = min(bd, end - base);
        float e = -INFINITY;
        int sj = 0;
        if (tid < cnt) {
            sj = g_csrc[base + tid];
            float x = g_el[sj] + er_n;
            e = x > 0.f ? x : 0.2f * x;
        }
        s_s[tid] = sj;
        s_red[tid] = e;
        __syncthreads();
        for (int o = bd >> 1; o > 0; o >>= 1) {
            if (tid < o) s_red[tid] = fmaxf(s_red[tid], s_red[tid + o]);
            __syncthreads();
        }
        float nm = fmaxf(m, s_red[0]);
        __syncthreads();

        float w = (tid < cnt) ? __expf(e - nm) : 0.f;
        s_w[tid] = w;
        s_red[tid] = w;
        __syncthreads();
        for (int o = bd >> 1; o > 0; o >>= 1) {
            if (tid < o) s_red[tid] += s_red[tid + o];
            __syncthreads();
        }
        float csum = s_red[0];

        float scale = (m == -INFINITY) ? 0.f : __expf(m - nm);
        ssum = ssum * scale + csum;
#pragma unroll
        for (int r = 0; r < NC; r++) acc[r] *= scale;

        for (int q = 0; q < cnt; q++) {
            float wq = s_w[q];
            const float* hr = H + (size_t)s_s[q] * dout;
#pragma unroll
            for (int r = 0; r < NC; r++)
                acc[r] += wq * hr[tid + r * bd];
        }
        m = nm;
        __syncthreads();
    }

    float inv = (end > beg) ? 1.f / ssum : 0.f;
#pragma unroll
    for (int r = 0; r < NC; r++) {
        int c = tid + r * bd;
        Y[(size_t)n * dout + c] = tanhf(acc[r] * inv + bias[c]);
    }
}

// ---------------- readout ----------------
__global__ void pool_kernel(const float* __restrict__ Y, const int* __restrict__ order) {
    int c = blockIdx.x * blockDim.x + threadIdx.x;   // 0..1023
    int rows = order[0] + 1;
    float s = 0.f;
    for (int r = 0; r < rows; r++) s += Y[(size_t)r * MAXD + c];
    g_pool[c] = s / (float)rows;
}

__global__ void logits_kernel(const float* __restrict__ relW,
                              const float* __restrict__ relB,
                              const int* __restrict__ rel,
                              float* __restrict__ out)
{
    int t = threadIdx.x;   // 64 threads
    float s = relB[t];
    for (int k = 0; k < MAXD; k++) s += g_pool[k] * relW[k * 64 + t];
    __shared__ float lg[64];
    lg[t] = s;
    __syncthreads();
    if (t == 0) {
        int idx[64];
        int cnt = 0;
        for (int i = 0; i < 64; i++)
            if (rel[i] != 0) idx[cnt++] = i;
        for (int k = cnt; k < 64; k++) idx[k] = 0;   // jnp.nonzero pad fill=0
        for (int k = 0; k < 64; k++) out[k] = lg[idx[k]];
    }
}

// ---------------- launch ----------------
extern "C" void kernel_launch(void* const* d_in, const int* in_sizes, int n_in,
                              void* d_out, int out_size)
{
    const float* feat  = (const float*)d_in[0];
    const float* W[4]  = {(const float*)d_in[1], (const float*)d_in[5],
                          (const float*)d_in[9], (const float*)d_in[13]};
    const float* al[4] = {(const float*)d_in[2], (const float*)d_in[6],
                          (const float*)d_in[10], (const float*)d_in[14]};
    const float* ar[4] = {(const float*)d_in[3], (const float*)d_in[7],
                          (const float*)d_in[11], (const float*)d_in[15]};
    const float* bb[4] = {(const float*)d_in[4], (const float*)d_in[8],
                          (const float*)d_in[12], (const float*)d_in[16]};
    const float* relW  = (const float*)d_in[17];
    const float* relB  = (const float*)d_in[18];
    const int*   src   = (const int*)d_in[19];
    const int*   dst   = (const int*)d_in[20];
    const int*   rel   = (const int*)d_in[21];
    const int*   order = (const int*)d_in[22];
    float* out = (float*)d_out;

    float *pA, *pB, *pH;
    cudaGetSymbolAddress((void**)&pA, g_bufA);
    cudaGetSymbolAddress((void**)&pB, g_bufB);
    cudaGetSymbolAddress((void**)&pH, g_H);

    // CSR (by dst) — rebuilt every launch, deterministic work
    zero_kernel <<<(N_NODES + 255) / 256, 256>>>();
    count_kernel<<<(N_EDGES + 255) / 256, 256>>>(dst);
    scan_kernel <<<1, 1024>>>();
    fill_kernel <<<(N_EDGES + 255) / 256, 256>>>(src, dst);

    const int din_a [4] = {64, 128, 256, 512};
    const int dout_a[4] = {128, 256, 512, 1024};

    const float* x = feat;
    float* outbufs[4] = {pA, pB, pA, pB};

    for (int l = 0; l < 4; l++) {
        int din = din_a[l], dout = dout_a[l];
        dim3 grid(dout / GBN, (N_NODES + GBM - 1) / GBM);
        gemm_tf32_kernel<<<grid, 256>>>(x, W[l], pH, N_NODES, din, dout);

        elr_kernel<<<(N_NODES * 32 + 255) / 256, 256>>>(pH, al[l], ar[l], dout);

        float* y = outbufs[l];
        switch (dout) {
            case 128:  agg_kernel<1><<<N_NODES, 128>>>(pH, bb[l], y, dout); break;
            case 256:  agg_kernel<1><<<N_NODES, 256>>>(pH, bb[l], y, dout); break;
            case 512:  agg_kernel<2><<<N_NODES, 256>>>(pH, bb[l], y, dout); break;
            default:   agg_kernel<4><<<N_NODES, 256>>>(pH, bb[l], y, dout); break;
        }
        x = y;
    }

    pool_kernel<<<MAXD / 256, 256>>>(pB, order);
    logits_kernel<<<1, 64>>>(relW, relB, rel, out);
}